// round 1
// baseline (speedup 1.0000x reference)
#include <cuda_runtime.h>
#include <math.h>

#define kB 64
#define kT 128
#define kU 256
#define kV 16000
#define kG 1024   /* 4*U */
#define kM 8192   /* B*T */

// ---------------- scratch (device globals; no allocation allowed) ----------
__device__ float g_Z0x[kT * kB * kG];        // 33.5 MB: x-part preactivations, layer 0
__device__ float g_Z1x[kT * kB * kG];        // 33.5 MB: x-part preactivations, layer 1
__device__ float g_H0[(kT + 1) * kB * kU];   // h history layer 0 (slot 0 = zeros)
__device__ float g_H1[(kT + 1) * kB * kU];   // h history layer 1
__device__ float g_C0[kB * kU];
__device__ float g_C1[kB * kU];
__device__ float g_Wt0[kG * kU];             // W0 h-part, transposed to [col][k]
__device__ float g_Wt1[kG * kU];             // W1 h-part, transposed
__device__ float g_S[kM];                    // per-token sum(exp(logit))
__device__ float g_TL[kM];                   // per-token target logit

// ---------------- init: zero states + sums ---------------------------------
__global__ void k_init() {
    int i = blockIdx.x * 256 + threadIdx.x;
    if (i < kB * kU) {
        g_C0[i] = 0.f; g_C1[i] = 0.f;
        g_H0[i] = 0.f; g_H1[i] = 0.f;   // slot 0 of history = initial h
    }
    if (i < kM) g_S[i] = 0.f;
}

// ---------------- transpose h-part of W: Wt[col][k] = W[U+k][col] ----------
__global__ void k_transpose(const float* __restrict__ W, int layer) {
    __shared__ float tile[32][33];
    float* Wt = layer ? g_Wt1 : g_Wt0;
    int col0 = blockIdx.x * 32, k0 = blockIdx.y * 32;
#pragma unroll
    for (int i = threadIdx.y; i < 32; i += 8)
        tile[i][threadIdx.x] = W[(kU + k0 + i) * kG + col0 + threadIdx.x];
    __syncthreads();
#pragma unroll
    for (int i = threadIdx.y; i < 32; i += 8)
        Wt[(long)(col0 + i) * kU + k0 + threadIdx.x] = tile[threadIdx.x][i];
}

// ---------------- Zx GEMM: Z[m][n] = A[m][:] @ W_x[:, n] + bias[n] ---------
// M=8192, N=1024, K=256.  layer 0: A row = embedding[input_data], gathered.
// layer 1: A = g_H0 rows 1..T (h0 outputs).
__global__ __launch_bounds__(256) void k_gemm_zx(
    int layer, const int* __restrict__ input_data, const float* __restrict__ emb,
    const float* __restrict__ W, const float* __restrict__ bias) {
    __shared__ float As[16][68];
    __shared__ float Bs[16][64];
    __shared__ const float* rowp[64];
    float* Z = layer ? g_Z1x : g_Z0x;
    int tx = threadIdx.x, ty = threadIdx.y;
    int tid = ty * 16 + tx;
    int m0 = blockIdx.y * 64, n0 = blockIdx.x * 64;
    if (tid < 64) {
        int m = m0 + tid;
        if (layer == 0) {
            int t = m >> 6, b = m & 63;   // m = t*64 + b
            rowp[tid] = emb + (long)input_data[b * kT + t] * kU;
        } else {
            rowp[tid] = g_H0 + kB * kU + (long)m * kU;
        }
    }
    __syncthreads();
    float acc[4][4];
#pragma unroll
    for (int i = 0; i < 4; i++)
#pragma unroll
        for (int j = 0; j < 4; j++) acc[i][j] = 0.f;

    for (int k0 = 0; k0 < kU; k0 += 16) {
#pragma unroll
        for (int p = 0; p < 4; p++) {
            int e = p * 256 + tid, r = e >> 4, c = e & 15;
            As[c][r] = rowp[r][k0 + c];
        }
#pragma unroll
        for (int p = 0; p < 4; p++) {
            int e = p * 256 + tid, kr = e >> 6, nc = e & 63;
            Bs[kr][nc] = W[(long)(k0 + kr) * kG + n0 + nc];
        }
        __syncthreads();
#pragma unroll
        for (int k = 0; k < 16; k++) {
            float4 a = *(const float4*)&As[k][ty * 4];
            float4 b = *(const float4*)&Bs[k][tx * 4];
            acc[0][0] += a.x * b.x; acc[0][1] += a.x * b.y; acc[0][2] += a.x * b.z; acc[0][3] += a.x * b.w;
            acc[1][0] += a.y * b.x; acc[1][1] += a.y * b.y; acc[1][2] += a.y * b.z; acc[1][3] += a.y * b.w;
            acc[2][0] += a.z * b.x; acc[2][1] += a.z * b.y; acc[2][2] += a.z * b.z; acc[2][3] += a.z * b.w;
            acc[3][0] += a.w * b.x; acc[3][1] += a.w * b.y; acc[3][2] += a.w * b.z; acc[3][3] += a.w * b.w;
        }
        __syncthreads();
    }
    float4 bb = *(const float4*)&bias[n0 + tx * 4];
#pragma unroll
    for (int i = 0; i < 4; i++) {
        float4 o = make_float4(acc[i][0] + bb.x, acc[i][1] + bb.y,
                               acc[i][2] + bb.z, acc[i][3] + bb.w);
        *(float4*)&Z[(long)(m0 + ty * 4 + i) * kG + n0 + tx * 4] = o;
    }
}

// ---------------- one LSTM step: z = Zx[t] + h_{t-1} @ W_h; gates ----------
// grid 64 blocks x 256 threads; block j owns u-columns [4j, 4j+4) for all b.
__global__ __launch_bounds__(256) void k_lstm_step(int t, int layer) {
    extern __shared__ float sm[];
    float* h_sm = sm;               // 64 x 260 (padded)
    float* w_sm = sm + 64 * 260;    // 16 x 264 (padded): rows = gate*4 + uu
    const float* zx = (layer ? g_Z1x : g_Z0x) + (long)t * kB * kG;
    const float* Wt = layer ? g_Wt1 : g_Wt0;
    float* H = layer ? g_H1 : g_H0;
    float* c = layer ? g_C1 : g_C0;
    const float* hprev = H + (long)t * kB * kU;
    float* hnext = H + (long)(t + 1) * kB * kU;
    int tid = threadIdx.x;
#pragma unroll
    for (int p = 0; p < 16; p++) {
        int e4 = p * 256 + tid, row = e4 >> 6, c4 = e4 & 63;
        float4 v = ((const float4*)hprev)[e4];
        *(float4*)&h_sm[row * 260 + c4 * 4] = v;
    }
    int u0 = blockIdx.x * 4;
#pragma unroll
    for (int rr = 0; rr < 16; rr++) {
        int g = rr >> 2, uu = rr & 3;
        w_sm[rr * 264 + tid] = Wt[(long)(g * kU + u0 + uu) * kU + tid];
    }
    __syncthreads();

    int b = tid >> 2, uu = tid & 3;
    const float4* hp = (const float4*)&h_sm[b * 260];
    const float4* w0 = (const float4*)&w_sm[(0 + uu) * 264];
    const float4* w1 = (const float4*)&w_sm[(4 + uu) * 264];
    const float4* w2 = (const float4*)&w_sm[(8 + uu) * 264];
    const float4* w3 = (const float4*)&w_sm[(12 + uu) * 264];
    float a0 = 0.f, a1 = 0.f, a2 = 0.f, a3 = 0.f;
#pragma unroll 8
    for (int k4 = 0; k4 < 64; k4++) {
        float4 hv = hp[k4];
        float4 v0 = w0[k4], v1 = w1[k4], v2 = w2[k4], v3 = w3[k4];
        a0 += hv.x * v0.x + hv.y * v0.y + hv.z * v0.z + hv.w * v0.w;
        a1 += hv.x * v1.x + hv.y * v1.y + hv.z * v1.z + hv.w * v1.w;
        a2 += hv.x * v2.x + hv.y * v2.y + hv.z * v2.z + hv.w * v2.w;
        a3 += hv.x * v3.x + hv.y * v3.y + hv.z * v3.z + hv.w * v3.w;
    }
    int u = u0 + uu;
    const float* z = zx + (long)b * kG;
    float zi = z[u] + a0;
    float zj = z[kU + u] + a1;
    float zf = z[2 * kU + u] + a2;
    float zo = z[3 * kU + u] + a3;
    float ii = 1.f / (1.f + __expf(-zi));
    float gg = tanhf(zj);
    float ff = 1.f / (1.f + __expf(-(zf + 1.f)));   // FORGET_BIAS = 1
    float oo = 1.f / (1.f + __expf(-zo));
    int off = b * kU + u;
    float cn = c[off] * ff + ii * gg;
    c[off] = cn;
    hnext[off] = tanhf(cn) * oo;
}

// ---------------- fused logits GEMM + sum(exp) + target logit --------------
// C[8192,16000] = H1 @ SW + sb; accumulate per-row sum(exp), grab target col.
__global__ __launch_bounds__(256) void k_logits(
    const int* __restrict__ targets, const float* __restrict__ SW,
    const float* __restrict__ sb) {
    __shared__ float As[16][68];
    __shared__ float Bs[16][128];
    int tx = threadIdx.x, ty = threadIdx.y;
    int tid = ty * 16 + tx;
    int m0 = blockIdx.y * 64, n0 = blockIdx.x * 128;
    const float* A = g_H1 + kB * kU;
    float acc[4][8];
#pragma unroll
    for (int i = 0; i < 4; i++)
#pragma unroll
        for (int j = 0; j < 8; j++) acc[i][j] = 0.f;

    for (int k0 = 0; k0 < kU; k0 += 16) {
#pragma unroll
        for (int p = 0; p < 4; p++) {
            int e = p * 256 + tid, r = e >> 4, c = e & 15;
            As[c][r] = A[(long)(m0 + r) * kU + k0 + c];
        }
#pragma unroll
        for (int p = 0; p < 8; p++) {
            int e = p * 256 + tid, kr = e >> 7, nc = e & 127;
            Bs[kr][nc] = SW[(long)(k0 + kr) * kV + n0 + nc];
        }
        __syncthreads();
#pragma unroll
        for (int k = 0; k < 16; k++) {
            float4 a  = *(const float4*)&As[k][ty * 4];
            float4 b0 = *(const float4*)&Bs[k][tx * 4];
            float4 b1 = *(const float4*)&Bs[k][64 + tx * 4];
            acc[0][0] += a.x * b0.x; acc[0][1] += a.x * b0.y; acc[0][2] += a.x * b0.z; acc[0][3] += a.x * b0.w;
            acc[1][0] += a.y * b0.x; acc[1][1] += a.y * b0.y; acc[1][2] += a.y * b0.z; acc[1][3] += a.y * b0.w;
            acc[2][0] += a.z * b0.x; acc[2][1] += a.z * b0.y; acc[2][2] += a.z * b0.z; acc[2][3] += a.z * b0.w;
            acc[3][0] += a.w * b0.x; acc[3][1] += a.w * b0.y; acc[3][2] += a.w * b0.z; acc[3][3] += a.w * b0.w;
            acc[0][4] += a.x * b1.x; acc[0][5] += a.x * b1.y; acc[0][6] += a.x * b1.z; acc[0][7] += a.x * b1.w;
            acc[1][4] += a.y * b1.x; acc[1][5] += a.y * b1.y; acc[1][6] += a.y * b1.z; acc[1][7] += a.y * b1.w;
            acc[2][4] += a.z * b1.x; acc[2][5] += a.z * b1.y; acc[2][6] += a.z * b1.z; acc[2][7] += a.z * b1.w;
            acc[3][4] += a.w * b1.x; acc[3][5] += a.w * b1.y; acc[3][6] += a.w * b1.z; acc[3][7] += a.w * b1.w;
        }
        __syncthreads();
    }
    float4 s0 = *(const float4*)&sb[n0 + tx * 4];
    float4 s1 = *(const float4*)&sb[n0 + 64 + tx * 4];
    float sbv[8] = {s0.x, s0.y, s0.z, s0.w, s1.x, s1.y, s1.z, s1.w};
    int cols[8];
#pragma unroll
    for (int j = 0; j < 4; j++) { cols[j] = n0 + tx * 4 + j; cols[4 + j] = n0 + 64 + tx * 4 + j; }
#pragma unroll
    for (int i = 0; i < 4; i++) {
        int gm = m0 + ty * 4 + i;
        int t = gm >> 6, b = gm & 63;
        int tg = targets[b * kT + t];
        float rs = 0.f;
#pragma unroll
        for (int j = 0; j < 8; j++) {
            float lg = acc[i][j] + sbv[j];
            if (cols[j] == tg) g_TL[gm] = lg;
            rs += __expf(lg);
        }
        rs += __shfl_xor_sync(0xffffffffu, rs, 8);
        rs += __shfl_xor_sync(0xffffffffu, rs, 4);
        rs += __shfl_xor_sync(0xffffffffu, rs, 2);
        rs += __shfl_xor_sync(0xffffffffu, rs, 1);
        if (tx == 0) atomicAdd(&g_S[gm], rs);
    }
}

// ---------------- final: cost = mean(log(S) - target_logit) ----------------
__global__ void k_final(float* __restrict__ out) {
    __shared__ float red[256];
    int tid = threadIdx.x;
    float acc = 0.f;
    for (int r = tid; r < kM; r += 256) acc += logf(g_S[r]) - g_TL[r];
    red[tid] = acc;
    __syncthreads();
    for (int s = 128; s > 0; s >>= 1) {
        if (tid < s) red[tid] += red[tid + s];
        __syncthreads();
    }
    if (tid == 0) out[0] = red[0] / (float)kM;
}

// ---------------- launch ----------------------------------------------------
extern "C" void kernel_launch(void* const* d_in, const int* in_sizes, int n_in,
                              void* d_out, int out_size) {
    const int*   input_data = (const int*)d_in[0];
    const int*   targets    = (const int*)d_in[1];
    const float* emb        = (const float*)d_in[2];
    const float* W0         = (const float*)d_in[3];
    const float* b0         = (const float*)d_in[4];
    const float* W1         = (const float*)d_in[5];
    const float* b1         = (const float*)d_in[6];
    const float* sw         = (const float*)d_in[7];
    const float* sb         = (const float*)d_in[8];
    float* out = (float*)d_out;

    const int lstm_smem = (64 * 260 + 16 * 264) * 4;  // 83456 B
    cudaFuncSetAttribute(k_lstm_step, cudaFuncAttributeMaxDynamicSharedMemorySize, lstm_smem);

    k_init<<<64, 256>>>();
    k_transpose<<<dim3(32, 8), dim3(32, 8)>>>(W0, 0);
    k_transpose<<<dim3(32, 8), dim3(32, 8)>>>(W1, 1);

    k_gemm_zx<<<dim3(16, 128), dim3(16, 16)>>>(0, input_data, emb, W0, b0);
    for (int t = 0; t < kT; t++) k_lstm_step<<<64, 256, lstm_smem>>>(t, 0);
    k_gemm_zx<<<dim3(16, 128), dim3(16, 16)>>>(1, input_data, emb, W1, b1);
    for (int t = 0; t < kT; t++) k_lstm_step<<<64, 256, lstm_smem>>>(t, 1);

    k_logits<<<dim3(125, 128), dim3(16, 16)>>>(targets, sw, sb);
    k_final<<<1, 256>>>(out);
}

// round 2
// speedup vs baseline: 1.0109x; 1.0109x over previous
#include <cuda_runtime.h>
#include <math.h>
#include <stdint.h>

#define kB 64
#define kT 128
#define kU 256
#define kV 16000
#define kG 1024   /* 4*U */
#define kM 8192   /* B*T */
#define NBLK 128  /* persistent LSTM blocks */

// ---------------- scratch (device globals; no allocation allowed) ----------
__device__ __align__(16) float g_Z0x[kT * kB * kG];
__device__ __align__(16) float g_Z1x[kT * kB * kG];
__device__ __align__(16) float g_H0[(kT + 1) * kB * kU];
__device__ __align__(16) float g_H1[(kT + 1) * kB * kU];
__device__ __align__(16) float g_Wt0[kG * kU];
__device__ __align__(16) float g_Wt1[kG * kU];
__device__ float g_S[kM];
__device__ float g_TL[kM];
__device__ unsigned g_barrier;

__device__ __forceinline__ float sigmoidf_(float x) { return 1.f / (1.f + __expf(-x)); }

__device__ __forceinline__ uint32_t f2tf32(float x) {
    uint32_t u; asm("cvt.rna.tf32.f32 %0, %1;" : "=r"(u) : "f"(x)); return u;
}

// ---------------- init: zero states + sums + barrier ------------------------
__global__ void k_init() {
    int i = blockIdx.x * 256 + threadIdx.x;
    if (i < kB * kU) { g_H0[i] = 0.f; g_H1[i] = 0.f; }
    if (i < kM) g_S[i] = 0.f;
    if (i == 0) g_barrier = 0u;
}

// ---------------- transpose h-part of W: Wt[col][k] = W[U+k][col] ----------
__global__ void k_transpose(const float* __restrict__ W, int layer) {
    __shared__ float tile[32][33];
    float* Wt = layer ? g_Wt1 : g_Wt0;
    int col0 = blockIdx.x * 32, k0 = blockIdx.y * 32;
#pragma unroll
    for (int i = threadIdx.y; i < 32; i += 8)
        tile[i][threadIdx.x] = W[(kU + k0 + i) * kG + col0 + threadIdx.x];
    __syncthreads();
#pragma unroll
    for (int i = threadIdx.y; i < 32; i += 8)
        Wt[(long)(col0 + i) * kU + k0 + threadIdx.x] = tile[threadIdx.x][i];
}

// ---------------- Zx GEMM: Z[m][n] = A[m][:] @ W_x[:, n] + bias[n] ---------
__global__ __launch_bounds__(256) void k_gemm_zx(
    int layer, const int* __restrict__ input_data, const float* __restrict__ emb,
    const float* __restrict__ W, const float* __restrict__ bias) {
    __shared__ float As[16][68];
    __shared__ float Bs[16][64];
    __shared__ const float* rowp[64];
    float* Z = layer ? g_Z1x : g_Z0x;
    int tx = threadIdx.x, ty = threadIdx.y;
    int tid = ty * 16 + tx;
    int m0 = blockIdx.y * 64, n0 = blockIdx.x * 64;
    if (tid < 64) {
        int m = m0 + tid;
        if (layer == 0) {
            int t = m >> 6, b = m & 63;
            rowp[tid] = emb + (long)input_data[b * kT + t] * kU;
        } else {
            rowp[tid] = g_H0 + kB * kU + (long)m * kU;
        }
    }
    __syncthreads();
    float acc[4][4];
#pragma unroll
    for (int i = 0; i < 4; i++)
#pragma unroll
        for (int j = 0; j < 4; j++) acc[i][j] = 0.f;

    for (int k0 = 0; k0 < kU; k0 += 16) {
#pragma unroll
        for (int p = 0; p < 4; p++) {
            int e = p * 256 + tid, r = e >> 4, c = e & 15;
            As[c][r] = rowp[r][k0 + c];
        }
#pragma unroll
        for (int p = 0; p < 4; p++) {
            int e = p * 256 + tid, kr = e >> 6, nc = e & 63;
            Bs[kr][nc] = W[(long)(k0 + kr) * kG + n0 + nc];
        }
        __syncthreads();
#pragma unroll
        for (int k = 0; k < 16; k++) {
            float4 a = *(const float4*)&As[k][ty * 4];
            float4 b = *(const float4*)&Bs[k][tx * 4];
            acc[0][0] += a.x * b.x; acc[0][1] += a.x * b.y; acc[0][2] += a.x * b.z; acc[0][3] += a.x * b.w;
            acc[1][0] += a.y * b.x; acc[1][1] += a.y * b.y; acc[1][2] += a.y * b.z; acc[1][3] += a.y * b.w;
            acc[2][0] += a.z * b.x; acc[2][1] += a.z * b.y; acc[2][2] += a.z * b.z; acc[2][3] += a.z * b.w;
            acc[3][0] += a.w * b.x; acc[3][1] += a.w * b.y; acc[3][2] += a.w * b.z; acc[3][3] += a.w * b.w;
        }
        __syncthreads();
    }
    float4 bb = *(const float4*)&bias[n0 + tx * 4];
#pragma unroll
    for (int i = 0; i < 4; i++) {
        float4 o = make_float4(acc[i][0] + bb.x, acc[i][1] + bb.y,
                               acc[i][2] + bb.z, acc[i][3] + bb.w);
        *(float4*)&Z[(long)(m0 + ty * 4 + i) * kG + n0 + tx * 4] = o;
    }
}

// ---------------- persistent LSTM layer: all 128 steps in one kernel -------
// 128 blocks (one per SM, all resident), software grid barrier between steps.
// Block owns u-columns {2*bx, 2*bx+1}. Thread: b=tid>>2, q=tid&3,
// uu=q>>1, half=q&1 -> computes gates {2*half, 2*half+1} for (b, u0+uu).
__global__ __launch_bounds__(256) void k_lstm_layer(int layer, int sync_base) {
    extern __shared__ float sm[];
    float* h_sm = sm;               // 64 x 260 (padded)
    float* w_sm = sm + 64 * 260;    // 8 x 256
    const float* Zx = layer ? g_Z1x : g_Z0x;
    const float* Wt = layer ? g_Wt1 : g_Wt0;
    float* H = layer ? g_H1 : g_H0;
    const int tid = threadIdx.x;
    const int u0 = blockIdx.x * 2;
    const int b = tid >> 2;
    const int q = tid & 3;
    const int uu = q >> 1;
    const int half = q & 1;
    const int u = u0 + uu;

    // load this block's 8 weight rows once (persist across all steps)
#pragma unroll
    for (int rr = 0; rr < 8; rr++) {
        int g = rr >> 1, wu = rr & 1;
        w_sm[rr * 256 + tid] = Wt[(long)(g * kU + u0 + wu) * kU + tid];
    }
    const float4* wA = (const float4*)&w_sm[(4 * half + uu) * 256];
    const float4* wB = (const float4*)&w_sm[(4 * half + 2 + uu) * 256];
    const float4* hp = (const float4*)&h_sm[b * 260];
    float creg = 0.f;

    for (int t = 0; t < kT; t++) {
        if (t > 0) {
            __syncthreads();
            if (tid == 0) {
                __threadfence();
                atomicAdd(&g_barrier, 1u);
                unsigned goal = (unsigned)(sync_base + t) * NBLK;
                unsigned v;
                do {
                    asm volatile("ld.acquire.gpu.u32 %0, [%1];" : "=r"(v) : "l"(&g_barrier));
                } while (v < goal);
            }
            __syncthreads();
        }
        // load h_{t-1} (written by all blocks) into smem
        const float4* hg = (const float4*)(H + (long)t * kB * kU);
#pragma unroll
        for (int p = 0; p < 16; p++) {
            int e = p * 256 + tid;
            int row = e >> 6, c4 = e & 63;
            float4 v = hg[e];
            *(float4*)&h_sm[row * 260 + c4 * 4] = v;
        }
        __syncthreads();

        float a0 = 0.f, a1 = 0.f;
#pragma unroll 8
        for (int k = 0; k < 64; k++) {
            float4 hv = hp[k];
            float4 va = wA[k], vb = wB[k];
            a0 += hv.x * va.x + hv.y * va.y + hv.z * va.z + hv.w * va.w;
            a1 += hv.x * vb.x + hv.y * vb.y + hv.z * vb.z + hv.w * vb.w;
        }
        const float* z = Zx + (long)t * kB * kG + (long)b * kG;
        float z0 = z[(2 * half) * kU + u] + a0;
        float z1 = z[(2 * half + 1) * kU + u] + a1;
        float send, ff = 0.f, oo = 0.f;
        if (half == 0) {
            send = sigmoidf_(z0) * tanhf(z1);   // sigmoid(i)*tanh(j)
        } else {
            ff = sigmoidf_(z0 + 1.f);           // FORGET_BIAS = 1
            oo = sigmoidf_(z1);
            send = 0.f;
        }
        float ig = __shfl_xor_sync(0xffffffffu, send, 1);
        if (half == 1) {
            creg = creg * ff + ig;
            H[(long)(t + 1) * kB * kU + (long)b * kU + u] = tanhf(creg) * oo;
        }
    }
}

// ---------------- fused logits GEMM (tf32 mma) + sum(exp) + target ---------
// 128x128 block tile, 8 warps (4M x 2N), warp tile 32x64, K=256 in 8 chunks.
__global__ __launch_bounds__(256) void k_logits_tf32(
    const int* __restrict__ targets, const float* __restrict__ SW,
    const float* __restrict__ sb) {
    extern __shared__ float sm[];
    float* As = sm;                  // 2 buffers of 128x36
    float* Bs = sm + 2 * 128 * 36;   // 2 buffers of 32x136
    const float* __restrict__ A = g_H1 + kB * kU;
    const int tid = threadIdx.x;
    const int lane = tid & 31;
    const int w = tid >> 5;
    const int warpM = w & 3;
    const int warpN = w >> 2;
    const int m0 = blockIdx.y * 128;
    const int n0 = blockIdx.x * 128;
    const int r = lane >> 2, cq = lane & 3;

    float acc[2][8][4];
#pragma unroll
    for (int i = 0; i < 2; i++)
#pragma unroll
        for (int j = 0; j < 8; j++)
#pragma unroll
            for (int k = 0; k < 4; k++) acc[i][j][k] = 0.f;

    float4 ra[4], rb[4];
    auto loadG = [&](int kc) {
#pragma unroll
        for (int p = 0; p < 4; p++) {
            int e = p * 256 + tid;
            ra[p] = *(const float4*)&A[(long)(m0 + (e >> 3)) * kU + kc * 32 + (e & 7) * 4];
        }
#pragma unroll
        for (int p = 0; p < 4; p++) {
            int e = p * 256 + tid;
            rb[p] = *(const float4*)&SW[(long)(kc * 32 + (e >> 5)) * kV + n0 + (e & 31) * 4];
        }
    };
    auto storeS = [&](int buf) {
        float* Ab = As + buf * 128 * 36;
        float* Bb = Bs + buf * 32 * 136;
#pragma unroll
        for (int p = 0; p < 4; p++) {
            int e = p * 256 + tid;
            *(float4*)&Ab[(e >> 3) * 36 + (e & 7) * 4] = ra[p];
        }
#pragma unroll
        for (int p = 0; p < 4; p++) {
            int e = p * 256 + tid;
            *(float4*)&Bb[(e >> 5) * 136 + (e & 31) * 4] = rb[p];
        }
    };

    loadG(0);
    storeS(0);
    __syncthreads();

    for (int kc = 0; kc < 8; kc++) {
        int buf = kc & 1;
        if (kc < 7) loadG(kc + 1);
        const float* Ab = As + buf * 128 * 36;
        const float* Bb = Bs + buf * 32 * 136;
#pragma unroll
        for (int kk = 0; kk < 4; kk++) {
            uint32_t af[2][4];
#pragma unroll
            for (int mi = 0; mi < 2; mi++) {
                const float* ap = &Ab[(warpM * 32 + mi * 16 + r) * 36 + kk * 8 + cq];
                af[mi][0] = f2tf32(ap[0]);
                af[mi][1] = f2tf32(ap[8 * 36]);
                af[mi][2] = f2tf32(ap[4]);
                af[mi][3] = f2tf32(ap[8 * 36 + 4]);
            }
#pragma unroll
            for (int ni = 0; ni < 8; ni++) {
                const float* bp = &Bb[(kk * 8 + cq) * 136 + warpN * 64 + ni * 8 + r];
                uint32_t b0 = f2tf32(bp[0]);
                uint32_t b1 = f2tf32(bp[4 * 136]);
#pragma unroll
                for (int mi = 0; mi < 2; mi++) {
                    asm volatile(
                        "mma.sync.aligned.m16n8k8.row.col.f32.tf32.tf32.f32 "
                        "{%0,%1,%2,%3}, {%4,%5,%6,%7}, {%8,%9}, {%0,%1,%2,%3};\n"
                        : "+f"(acc[mi][ni][0]), "+f"(acc[mi][ni][1]),
                          "+f"(acc[mi][ni][2]), "+f"(acc[mi][ni][3])
                        : "r"(af[mi][0]), "r"(af[mi][1]), "r"(af[mi][2]), "r"(af[mi][3]),
                          "r"(b0), "r"(b1));
                }
            }
        }
        if (kc < 7) { storeS(buf ^ 1); __syncthreads(); }
    }

    // epilogue: bias, target grab, sum(exp) per row over this warp's 64 cols
#pragma unroll
    for (int mi = 0; mi < 2; mi++) {
#pragma unroll
        for (int hh = 0; hh < 2; hh++) {
            int gm = m0 + warpM * 32 + mi * 16 + r + 8 * hh;
            int tt = gm >> 6, bb = gm & 63;
            int tg = targets[bb * kT + tt];
            float s = 0.f;
#pragma unroll
            for (int ni = 0; ni < 8; ni++) {
                int col = n0 + warpN * 64 + ni * 8 + cq * 2;
                float l0 = acc[mi][ni][hh * 2 + 0] + sb[col];
                float l1 = acc[mi][ni][hh * 2 + 1] + sb[col + 1];
                if (col == tg) g_TL[gm] = l0;
                if (col + 1 == tg) g_TL[gm] = l1;
                s += __expf(l0) + __expf(l1);
            }
            s += __shfl_xor_sync(0xffffffffu, s, 1);
            s += __shfl_xor_sync(0xffffffffu, s, 2);
            if (cq == 0) atomicAdd(&g_S[gm], s);
        }
    }
}

// ---------------- final: cost = mean(log(S) - target_logit) ----------------
__global__ void k_final(float* __restrict__ out) {
    __shared__ float red[256];
    int tid = threadIdx.x;
    float acc = 0.f;
    for (int rr = tid; rr < kM; rr += 256) acc += logf(g_S[rr]) - g_TL[rr];
    red[tid] = acc;
    __syncthreads();
    for (int s = 128; s > 0; s >>= 1) {
        if (tid < s) red[tid] += red[tid + s];
        __syncthreads();
    }
    if (tid == 0) out[0] = red[0] / (float)kM;
}

// ---------------- launch ----------------------------------------------------
extern "C" void kernel_launch(void* const* d_in, const int* in_sizes, int n_in,
                              void* d_out, int out_size) {
    const int*   input_data = (const int*)d_in[0];
    const int*   targets    = (const int*)d_in[1];
    const float* emb        = (const float*)d_in[2];
    const float* W0         = (const float*)d_in[3];
    const float* b0         = (const float*)d_in[4];
    const float* W1         = (const float*)d_in[5];
    const float* b1         = (const float*)d_in[6];
    const float* sw         = (const float*)d_in[7];
    const float* sb         = (const float*)d_in[8];
    float* out = (float*)d_out;

    const int lstm_smem   = (64 * 260 + 8 * 256) * 4;               // 74752 B
    const int logits_smem = (2 * 128 * 36 + 2 * 32 * 136) * 4;      // 71680 B
    cudaFuncSetAttribute(k_lstm_layer, cudaFuncAttributeMaxDynamicSharedMemorySize, lstm_smem);
    cudaFuncSetAttribute(k_logits_tf32, cudaFuncAttributeMaxDynamicSharedMemorySize, logits_smem);

    k_init<<<64, 256>>>();
    k_transpose<<<dim3(32, 8), dim3(32, 8)>>>(W0, 0);
    k_transpose<<<dim3(32, 8), dim3(32, 8)>>>(W1, 1);

    k_gemm_zx<<<dim3(16, 128), dim3(16, 16)>>>(0, input_data, emb, W0, b0);
    k_lstm_layer<<<NBLK, 256, lstm_smem>>>(0, 0);
    k_gemm_zx<<<dim3(16, 128), dim3(16, 16)>>>(1, input_data, emb, W1, b1);
    k_lstm_layer<<<NBLK, 256, lstm_smem>>>(1, kT - 1);

    k_logits_tf32<<<dim3(125, 64), 256, logits_smem>>>(targets, sw, sb);
    k_final<<<1, 256>>>(out);
}

// round 3
// speedup vs baseline: 2.0518x; 2.0296x over previous
#include <cuda_runtime.h>
#include <math.h>
#include <stdint.h>

#define kB 64
#define kT 128
#define kU 256
#define kV 16000
#define kG 1024   /* 4*U */
#define kM 8192   /* B*T */

// ---------------- scratch (device globals; no allocation allowed) ----------
__device__ __align__(16) float g_Z0x[kT * kB * kG];
__device__ __align__(16) float g_Z1x[kT * kB * kG];
__device__ __align__(16) float g_H0[(kT + 1) * kB * kU];
__device__ __align__(16) float g_H1[(kT + 1) * kB * kU];
__device__ __align__(16) float g_Wt0[kG * kU];
__device__ __align__(16) float g_Wt1[kG * kU];
__device__ float g_S[kM];
__device__ float g_TL[kM];
__device__ unsigned g_bar[8];

__device__ __forceinline__ float sigmoidf_(float x) { return 1.f / (1.f + __expf(-x)); }

__device__ __forceinline__ uint32_t f2tf32(float x) {
    uint32_t u; asm("cvt.rna.tf32.f32 %0, %1;" : "=r"(u) : "f"(x)); return u;
}

__global__ void k_dummy() {}

// ---------------- init: zero states + sums + barriers -----------------------
__global__ void k_init() {
    int i = blockIdx.x * 256 + threadIdx.x;
    if (i < kB * kU) { g_H0[i] = 0.f; g_H1[i] = 0.f; }
    if (i < kM) g_S[i] = 0.f;
    if (i < 8) g_bar[i] = 0u;
}

// ---------------- transpose h-part of W: Wt[col][k] = W[U+k][col] ----------
__global__ void k_transpose(const float* __restrict__ W, int layer) {
    __shared__ float tile[32][33];
    float* Wt = layer ? g_Wt1 : g_Wt0;
    int col0 = blockIdx.x * 32, k0 = blockIdx.y * 32;
#pragma unroll
    for (int i = threadIdx.y; i < 32; i += 8)
        tile[i][threadIdx.x] = W[(kU + k0 + i) * kG + col0 + threadIdx.x];
    __syncthreads();
#pragma unroll
    for (int i = threadIdx.y; i < 32; i += 8)
        Wt[(long)(col0 + i) * kU + k0 + threadIdx.x] = tile[threadIdx.x][i];
}

// ---------------- Zx GEMM: Z[m][n] = A[m][:] @ W_x[:, n] + bias[n] ---------
__global__ __launch_bounds__(256) void k_gemm_zx(
    int layer, const int* __restrict__ input_data, const float* __restrict__ emb,
    const float* __restrict__ W, const float* __restrict__ bias) {
    __shared__ float As[16][68];
    __shared__ float Bs[16][64];
    __shared__ const float* rowp[64];
    float* Z = layer ? g_Z1x : g_Z0x;
    int tx = threadIdx.x, ty = threadIdx.y;
    int tid = ty * 16 + tx;
    int m0 = blockIdx.y * 64, n0 = blockIdx.x * 64;
    if (tid < 64) {
        int m = m0 + tid;
        if (layer == 0) {
            int t = m >> 6, b = m & 63;
            rowp[tid] = emb + (long)input_data[b * kT + t] * kU;
        } else {
            rowp[tid] = g_H0 + kB * kU + (long)m * kU;
        }
    }
    __syncthreads();
    float acc[4][4];
#pragma unroll
    for (int i = 0; i < 4; i++)
#pragma unroll
        for (int j = 0; j < 4; j++) acc[i][j] = 0.f;

    for (int k0 = 0; k0 < kU; k0 += 16) {
#pragma unroll
        for (int p = 0; p < 4; p++) {
            int e = p * 256 + tid, r = e >> 4, c = e & 15;
            As[c][r] = rowp[r][k0 + c];
        }
#pragma unroll
        for (int p = 0; p < 4; p++) {
            int e = p * 256 + tid, kr = e >> 6, nc = e & 63;
            Bs[kr][nc] = W[(long)(k0 + kr) * kG + n0 + nc];
        }
        __syncthreads();
#pragma unroll
        for (int k = 0; k < 16; k++) {
            float4 a = *(const float4*)&As[k][ty * 4];
            float4 b = *(const float4*)&Bs[k][tx * 4];
            acc[0][0] += a.x * b.x; acc[0][1] += a.x * b.y; acc[0][2] += a.x * b.z; acc[0][3] += a.x * b.w;
            acc[1][0] += a.y * b.x; acc[1][1] += a.y * b.y; acc[1][2] += a.y * b.z; acc[1][3] += a.y * b.w;
            acc[2][0] += a.z * b.x; acc[2][1] += a.z * b.y; acc[2][2] += a.z * b.z; acc[2][3] += a.z * b.w;
            acc[3][0] += a.w * b.x; acc[3][1] += a.w * b.y; acc[3][2] += a.w * b.z; acc[3][3] += a.w * b.w;
        }
        __syncthreads();
    }
    float4 bb = *(const float4*)&bias[n0 + tx * 4];
#pragma unroll
    for (int i = 0; i < 4; i++) {
        float4 o = make_float4(acc[i][0] + bb.x, acc[i][1] + bb.y,
                               acc[i][2] + bb.z, acc[i][3] + bb.w);
        *(float4*)&Z[(long)(m0 + ty * 4 + i) * kG + n0 + tx * 4] = o;
    }
}

// ---------------- persistent LSTM layer -------------------------------------
// 128 blocks = 8 row-groups x 16 u-blocks. Block: 8 batch rows x 16 u (x4 gates).
// Weights (64 zcols x 256) live in smem for all 128 steps. Barrier per row-group
// (16 blocks). Warp: (ug 0..3, kh 0..1); lane: (row 0..7, usub 0..3).
__global__ __launch_bounds__(256) void k_lstm_layer(int layer, int sync_base) {
    extern __shared__ char smraw[];
    float4* w4 = (float4*)smraw;           // 64 x 65
    float4* h4 = w4 + 64 * 65;             // 8 x 65
    float*  red = (float*)(h4 + 8 * 65);   // 2 x 8 x 16 x 4 floats

    const int tid = threadIdx.x;
    const int bx = blockIdx.x;
    const int rg = bx >> 4;        // row-group 0..7
    const int ub = bx & 15;        // u-block 0..15
    const int r0 = rg * 8;
    const int u0 = ub * 16;
    const float* Zx = layer ? g_Z1x : g_Z0x;
    const float* Wt = layer ? g_Wt1 : g_Wt0;
    float* H = layer ? g_H1 : g_H0;
    const float4* Wt4 = (const float4*)Wt;

    // load this block's 64 weight rows once: zrow = g*16 + uq
#pragma unroll
    for (int p = 0; p < 16; p++) {
        int e = p * 256 + tid;
        int zrow = e >> 6, kf4 = e & 63;
        int g = zrow >> 4, uq = zrow & 15;
        w4[zrow * 65 + kf4] = Wt4[(size_t)(g * kU + u0 + uq) * 64 + kf4];
    }

    const int w = tid >> 5, lane = tid & 31;
    const int ug = w & 3, kh = w >> 2;        // ug: u-quad, kh: K half
    const int row = lane >> 2, usub = lane & 3;
    const int uu = ug * 4 + usub;             // 0..15
    const float4* hrow  = h4 + row * 65 + kh * 32;
    const float4* wbase = w4 + uu * 65 + kh * 32;

    float creg = 0.f;   // cell state for epilogue threads (tid<128)

    for (int t = 0; t < kT; t++) {
        if (t > 0) {
            __syncthreads();
            if (tid == 0) {
                atomicAdd(&g_bar[rg], 1u);
                unsigned goal = (unsigned)(sync_base + t) * 16u;
                unsigned v;
                do {
                    asm volatile("ld.acquire.gpu.u32 %0, [%1];" : "=r"(v) : "l"(&g_bar[rg]));
                } while (v < goal);
            }
            __syncthreads();
        }
        // load h_t rows r0..r0+7
        const float4* hg = (const float4*)(H + (size_t)t * kB * kU + (size_t)r0 * kU);
#pragma unroll
        for (int p = 0; p < 2; p++) {
            int e = p * 256 + tid;
            int hr = e >> 6, kf4 = e & 63;
            h4[hr * 65 + kf4] = hg[hr * 64 + kf4];
        }
        __syncthreads();

        float a0 = 0.f, a1 = 0.f, a2 = 0.f, a3 = 0.f;
#pragma unroll
        for (int k = 0; k < 32; k++) {
            float4 hv = hrow[k];
            float4 w0 = wbase[k];
            float4 w1 = wbase[16 * 65 + k];
            float4 w2 = wbase[32 * 65 + k];
            float4 w3 = wbase[48 * 65 + k];
            a0 += hv.x * w0.x + hv.y * w0.y + hv.z * w0.z + hv.w * w0.w;
            a1 += hv.x * w1.x + hv.y * w1.y + hv.z * w1.z + hv.w * w1.w;
            a2 += hv.x * w2.x + hv.y * w2.y + hv.z * w2.z + hv.w * w2.w;
            a3 += hv.x * w3.x + hv.y * w3.y + hv.z * w3.z + hv.w * w3.w;
        }
        *(float4*)&red[((kh * 8 + row) * 16 + uu) * 4] = make_float4(a0, a1, a2, a3);
        __syncthreads();

        if (tid < 128) {
            int er = tid >> 4, eu = tid & 15;
            float4 p0 = *(const float4*)&red[((0 * 8 + er) * 16 + eu) * 4];
            float4 p1 = *(const float4*)&red[((1 * 8 + er) * 16 + eu) * 4];
            const float* z = Zx + (size_t)t * kB * kG + (size_t)(r0 + er) * kG + u0 + eu;
            float zi = z[0]       + p0.x + p1.x;
            float zj = z[kU]      + p0.y + p1.y;
            float zf = z[2 * kU]  + p0.z + p1.z;
            float zo = z[3 * kU]  + p0.w + p1.w;
            float inj = sigmoidf_(zi) * tanhf(zj);
            creg = creg * sigmoidf_(zf + 1.f) + inj;   // FORGET_BIAS = 1
            H[(size_t)(t + 1) * kB * kU + (size_t)(r0 + er) * kU + u0 + eu] =
                tanhf(creg) * sigmoidf_(zo);
            __threadfence();
        }
    }
}

// ---------------- fused logits GEMM (tf32 mma) + sum(exp) + target ---------
// 256x128 block tile, 512 threads = 16 warps (8M x 2N), warp tile 32x64.
__global__ __launch_bounds__(512) void k_logits_tf32(
    const int* __restrict__ targets, const float* __restrict__ SW,
    const float* __restrict__ sb) {
    extern __shared__ float sm[];
    float* As = sm;                   // 2 buffers of 256x36
    float* Bs = sm + 2 * 256 * 36;    // 2 buffers of 32x136
    const float* __restrict__ A = g_H1 + kB * kU;
    const int tid = threadIdx.x;
    const int lane = tid & 31;
    const int w = tid >> 5;
    const int warpM = w & 7;
    const int warpN = w >> 3;
    const int m0 = blockIdx.y * 256;
    const int n0 = blockIdx.x * 128;
    const int r = lane >> 2, cq = lane & 3;

    float acc[2][8][4];
#pragma unroll
    for (int i = 0; i < 2; i++)
#pragma unroll
        for (int j = 0; j < 8; j++)
#pragma unroll
            for (int k = 0; k < 4; k++) acc[i][j][k] = 0.f;

    float4 ra[4], rb[2];
    auto loadG = [&](int kc) {
#pragma unroll
        for (int p = 0; p < 4; p++) {
            int e = p * 512 + tid;
            ra[p] = *(const float4*)&A[(long)(m0 + (e >> 3)) * kU + kc * 32 + (e & 7) * 4];
        }
#pragma unroll
        for (int p = 0; p < 2; p++) {
            int e = p * 512 + tid;
            rb[p] = *(const float4*)&SW[(long)(kc * 32 + (e >> 5)) * kV + n0 + (e & 31) * 4];
        }
    };
    auto storeS = [&](int buf) {
        float* Ab = As + buf * 256 * 36;
        float* Bb = Bs + buf * 32 * 136;
#pragma unroll
        for (int p = 0; p < 4; p++) {
            int e = p * 512 + tid;
            *(float4*)&Ab[(e >> 3) * 36 + (e & 7) * 4] = ra[p];
        }
#pragma unroll
        for (int p = 0; p < 2; p++) {
            int e = p * 512 + tid;
            *(float4*)&Bb[(e >> 5) * 136 + (e & 31) * 4] = rb[p];
        }
    };

    loadG(0);
    storeS(0);
    __syncthreads();

    for (int kc = 0; kc < 8; kc++) {
        int buf = kc & 1;
        if (kc < 7) loadG(kc + 1);
        const float* Ab = As + buf * 256 * 36;
        const float* Bb = Bs + buf * 32 * 136;
#pragma unroll
        for (int kk = 0; kk < 4; kk++) {
            uint32_t af[2][4];
#pragma unroll
            for (int mi = 0; mi < 2; mi++) {
                const float* ap = &Ab[(warpM * 32 + mi * 16 + r) * 36 + kk * 8 + cq];
                af[mi][0] = f2tf32(ap[0]);
                af[mi][1] = f2tf32(ap[8 * 36]);
                af[mi][2] = f2tf32(ap[4]);
                af[mi][3] = f2tf32(ap[8 * 36 + 4]);
            }
#pragma unroll
            for (int ni = 0; ni < 8; ni++) {
                const float* bp = &Bb[(kk * 8 + cq) * 136 + warpN * 64 + ni * 8 + r];
                uint32_t b0 = f2tf32(bp[0]);
                uint32_t b1 = f2tf32(bp[4 * 136]);
#pragma unroll
                for (int mi = 0; mi < 2; mi++) {
                    asm volatile(
                        "mma.sync.aligned.m16n8k8.row.col.f32.tf32.tf32.f32 "
                        "{%0,%1,%2,%3}, {%4,%5,%6,%7}, {%8,%9}, {%0,%1,%2,%3};\n"
                        : "+f"(acc[mi][ni][0]), "+f"(acc[mi][ni][1]),
                          "+f"(acc[mi][ni][2]), "+f"(acc[mi][ni][3])
                        : "r"(af[mi][0]), "r"(af[mi][1]), "r"(af[mi][2]), "r"(af[mi][3]),
                          "r"(b0), "r"(b1));
                }
            }
        }
        if (kc < 7) { storeS(buf ^ 1); __syncthreads(); }
    }

    // epilogue: bias, target grab, sum(exp) per row over this warp's 64 cols
#pragma unroll
    for (int mi = 0; mi < 2; mi++) {
#pragma unroll
        for (int hh = 0; hh < 2; hh++) {
            int gm = m0 + warpM * 32 + mi * 16 + r + 8 * hh;
            int tt = gm >> 6, bb = gm & 63;
            int tg = targets[bb * kT + tt];
            float s = 0.f;
#pragma unroll
            for (int ni = 0; ni < 8; ni++) {
                int col = n0 + warpN * 64 + ni * 8 + cq * 2;
                float l0 = acc[mi][ni][hh * 2 + 0] + sb[col];
                float l1 = acc[mi][ni][hh * 2 + 1] + sb[col + 1];
                if (col == tg) g_TL[gm] = l0;
                if (col + 1 == tg) g_TL[gm] = l1;
                s += __expf(l0) + __expf(l1);
            }
            s += __shfl_xor_sync(0xffffffffu, s, 1);
            s += __shfl_xor_sync(0xffffffffu, s, 2);
            if (cq == 0) atomicAdd(&g_S[gm], s);
        }
    }
}

// ---------------- final: cost = mean(log(S) - target_logit) ----------------
__global__ void k_final(float* __restrict__ out) {
    __shared__ float red[256];
    int tid = threadIdx.x;
    float acc = 0.f;
    for (int rr = tid; rr < kM; rr += 256) acc += logf(g_S[rr]) - g_TL[rr];
    red[tid] = acc;
    __syncthreads();
    for (int s = 128; s > 0; s >>= 1) {
        if (tid < s) red[tid] += red[tid + s];
        __syncthreads();
    }
    if (tid == 0) out[0] = red[0] / (float)kM;
}

// ---------------- launch ----------------------------------------------------
extern "C" void kernel_launch(void* const* d_in, const int* in_sizes, int n_in,
                              void* d_out, int out_size) {
    const int*   input_data = (const int*)d_in[0];
    const int*   targets    = (const int*)d_in[1];
    const float* emb        = (const float*)d_in[2];
    const float* W0         = (const float*)d_in[3];
    const float* b0         = (const float*)d_in[4];
    const float* W1         = (const float*)d_in[5];
    const float* b1         = (const float*)d_in[6];
    const float* sw         = (const float*)d_in[7];
    const float* sb         = (const float*)d_in[8];
    float* out = (float*)d_out;

    const int lstm_smem   = (64 * 65 + 8 * 65) * 16 + 2 * 8 * 16 * 4 * 4;   // 78976 B
    const int logits_smem = (2 * 256 * 36 + 2 * 32 * 136) * 4;              // 108544 B
    cudaFuncSetAttribute(k_lstm_layer, cudaFuncAttributeMaxDynamicSharedMemorySize, lstm_smem);
    cudaFuncSetAttribute(k_logits_tf32, cudaFuncAttributeMaxDynamicSharedMemorySize, logits_smem);

    k_dummy<<<1, 32>>>();   // shifts launch index so ncu (-s 5) captures lstm layer 0
    k_init<<<64, 256>>>();
    k_transpose<<<dim3(32, 8), dim3(32, 8)>>>(W0, 0);
    k_transpose<<<dim3(32, 8), dim3(32, 8)>>>(W1, 1);

    k_gemm_zx<<<dim3(16, 128), dim3(16, 16)>>>(0, input_data, emb, W0, b0);
    k_lstm_layer<<<128, 256, lstm_smem>>>(0, 0);
    k_gemm_zx<<<dim3(16, 128), dim3(16, 16)>>>(1, input_data, emb, W1, b1);
    k_lstm_layer<<<128, 256, lstm_smem>>>(1, kT - 1);

    k_logits_tf32<<<dim3(125, 32), 512, logits_smem>>>(targets, sw, sb);
    k_final<<<1, 256>>>(out);
}

// round 4
// speedup vs baseline: 2.3117x; 1.1266x over previous
#include <cuda_runtime.h>
#include <math.h>
#include <stdint.h>

#define kB 64
#define kT 128
#define kU 256
#define kV 16000
#define kG 1024   /* 4*U */
#define kM 8192   /* B*T */

// ---------------- scratch (device globals; no allocation allowed) ----------
__device__ __align__(16) float g_Z0x[kT * kB * kG];
__device__ __align__(16) float g_Z1x[kT * kB * kG];
__device__ __align__(16) float g_H0[(kT + 1) * kB * kU];
__device__ __align__(16) float g_H1[(kT + 1) * kB * kU];
__device__ __align__(16) float g_Wt0[kG * kU];
__device__ __align__(16) float g_Wt1[kG * kU];
__device__ float g_S[kM];
__device__ float g_TL[kM];
__device__ unsigned g_bar[8];

__device__ __forceinline__ float sigmoidf_(float x) { return 1.f / (1.f + __expf(-x)); }

__device__ __forceinline__ uint32_t f2tf32(float x) {
    uint32_t u; asm("cvt.rna.tf32.f32 %0, %1;" : "=r"(u) : "f"(x)); return u;
}

#define FMA2(acc, a, b) \
    asm("fma.rn.f32x2 %0, %1, %2, %0;" : "+l"(acc) : "l"(a), "l"(b))

// ---------------- init: zero states + sums + barriers -----------------------
__global__ void k_init() {
    int i = blockIdx.x * 256 + threadIdx.x;
    if (i < kB * kU) { g_H0[i] = 0.f; g_H1[i] = 0.f; }
    if (i < kM) g_S[i] = 0.f;
    if (i < 8) g_bar[i] = 0u;
}

// ---------------- transpose h-part of W: Wt[col][k] = W[U+k][col] ----------
__global__ void k_transpose(const float* __restrict__ W, int layer) {
    __shared__ float tile[32][33];
    float* Wt = layer ? g_Wt1 : g_Wt0;
    int col0 = blockIdx.x * 32, k0 = blockIdx.y * 32;
#pragma unroll
    for (int i = threadIdx.y; i < 32; i += 8)
        tile[i][threadIdx.x] = W[(kU + k0 + i) * kG + col0 + threadIdx.x];
    __syncthreads();
#pragma unroll
    for (int i = threadIdx.y; i < 32; i += 8)
        Wt[(long)(col0 + i) * kU + k0 + threadIdx.x] = tile[threadIdx.x][i];
}

// ---------------- Zx GEMM (tf32 mma): Z = A @ W_x + bias -------------------
// M=8192, N=1024, K=256. 256x128 tile, 512 threads (8M x 2N warps).
__global__ __launch_bounds__(512) void k_gemm_zx_tf32(
    int layer, const int* __restrict__ input_data, const float* __restrict__ emb,
    const float* __restrict__ W, const float* __restrict__ bias) {
    extern __shared__ float sm[];
    float* As = sm;                   // 2 buffers of 256x36
    float* Bs = sm + 2 * 256 * 36;    // 2 buffers of 32x136
    __shared__ const float* rowp[256];
    float* Z = layer ? g_Z1x : g_Z0x;
    const int tid = threadIdx.x;
    const int lane = tid & 31;
    const int w = tid >> 5;
    const int warpM = w & 7;
    const int warpN = w >> 3;
    const int m0 = blockIdx.y * 256;
    const int n0 = blockIdx.x * 128;
    const int r = lane >> 2, cq = lane & 3;

    if (tid < 256) {
        int m = m0 + tid;
        if (layer == 0) {
            int t = m >> 6, b = m & 63;
            rowp[tid] = emb + (size_t)input_data[b * kT + t] * kU;
        } else {
            rowp[tid] = g_H0 + kB * kU + (size_t)m * kU;
        }
    }
    __syncthreads();

    float acc[2][8][4];
#pragma unroll
    for (int i = 0; i < 2; i++)
#pragma unroll
        for (int j = 0; j < 8; j++)
#pragma unroll
            for (int k = 0; k < 4; k++) acc[i][j][k] = 0.f;

    float4 ra[4], rb[2];
    auto loadG = [&](int kc) {
#pragma unroll
        for (int p = 0; p < 4; p++) {
            int e = p * 512 + tid;
            ra[p] = *(const float4*)&rowp[e >> 3][kc * 32 + (e & 7) * 4];
        }
#pragma unroll
        for (int p = 0; p < 2; p++) {
            int e = p * 512 + tid;
            rb[p] = *(const float4*)&W[(size_t)(kc * 32 + (e >> 5)) * kG + n0 + (e & 31) * 4];
        }
    };
    auto storeS = [&](int buf) {
        float* Ab = As + buf * 256 * 36;
        float* Bb = Bs + buf * 32 * 136;
#pragma unroll
        for (int p = 0; p < 4; p++) {
            int e = p * 512 + tid;
            *(float4*)&Ab[(e >> 3) * 36 + (e & 7) * 4] = ra[p];
        }
#pragma unroll
        for (int p = 0; p < 2; p++) {
            int e = p * 512 + tid;
            *(float4*)&Bb[(e >> 5) * 136 + (e & 31) * 4] = rb[p];
        }
    };

    loadG(0);
    storeS(0);
    __syncthreads();

    for (int kc = 0; kc < 8; kc++) {
        int buf = kc & 1;
        if (kc < 7) loadG(kc + 1);
        const float* Ab = As + buf * 256 * 36;
        const float* Bb = Bs + buf * 32 * 136;
#pragma unroll
        for (int kk = 0; kk < 4; kk++) {
            uint32_t af[2][4];
#pragma unroll
            for (int mi = 0; mi < 2; mi++) {
                const float* ap = &Ab[(warpM * 32 + mi * 16 + r) * 36 + kk * 8 + cq];
                af[mi][0] = f2tf32(ap[0]);
                af[mi][1] = f2tf32(ap[8 * 36]);
                af[mi][2] = f2tf32(ap[4]);
                af[mi][3] = f2tf32(ap[8 * 36 + 4]);
            }
#pragma unroll
            for (int ni = 0; ni < 8; ni++) {
                const float* bp = &Bb[(kk * 8 + cq) * 136 + warpN * 64 + ni * 8 + r];
                uint32_t b0 = f2tf32(bp[0]);
                uint32_t b1 = f2tf32(bp[4 * 136]);
#pragma unroll
                for (int mi = 0; mi < 2; mi++) {
                    asm volatile(
                        "mma.sync.aligned.m16n8k8.row.col.f32.tf32.tf32.f32 "
                        "{%0,%1,%2,%3}, {%4,%5,%6,%7}, {%8,%9}, {%0,%1,%2,%3};\n"
                        : "+f"(acc[mi][ni][0]), "+f"(acc[mi][ni][1]),
                          "+f"(acc[mi][ni][2]), "+f"(acc[mi][ni][3])
                        : "r"(af[mi][0]), "r"(af[mi][1]), "r"(af[mi][2]), "r"(af[mi][3]),
                          "r"(b0), "r"(b1));
                }
            }
        }
        if (kc < 7) { storeS(buf ^ 1); __syncthreads(); }
    }

    // epilogue: + bias, store Z
#pragma unroll
    for (int ni = 0; ni < 8; ni++) {
        int col = n0 + warpN * 64 + ni * 8 + cq * 2;
        float2 bb = *(const float2*)&bias[col];
#pragma unroll
        for (int mi = 0; mi < 2; mi++) {
            int gm = m0 + warpM * 32 + mi * 16 + r;
            *(float2*)&Z[(size_t)gm * kG + col] =
                make_float2(acc[mi][ni][0] + bb.x, acc[mi][ni][1] + bb.y);
            *(float2*)&Z[(size_t)(gm + 8) * kG + col] =
                make_float2(acc[mi][ni][2] + bb.x, acc[mi][ni][3] + bb.y);
        }
    }
}

// ---------------- persistent LSTM layer -------------------------------------
// 128 blocks = 8 row-groups x 16 u-blocks; barrier per row-group (16 blocks).
// Thread owns 2 full-K dot products (gate pair gp for (row,u)); f32x2 FMA.
// Weight smem row index = g + 4*uq (bank-conflict-free for the 4 rows/warp).
__global__ __launch_bounds__(256) void k_lstm_layer(int layer, int sync_base) {
    extern __shared__ char smraw[];
    float4* w4 = (float4*)smraw;           // 64 x 65
    float4* h4 = w4 + 64 * 65;             // 8 x 65

    const int tid = threadIdx.x;
    const int bx = blockIdx.x;
    const int rg = bx >> 4, ub = bx & 15;
    const int r0 = rg * 8, u0 = ub * 16;
    const float* Zx = layer ? g_Z1x : g_Z0x;
    const float* Wt = layer ? g_Wt1 : g_Wt0;
    float* H = layer ? g_H1 : g_H0;
    const float4* Wt4 = (const float4*)Wt;

    // load 64 weight rows once; storage idx = g + 4*uq
#pragma unroll
    for (int p = 0; p < 16; p++) {
        int e = p * 256 + tid;
        int zrow = e >> 6, kf4 = e & 63;
        int g = zrow & 3, uq = zrow >> 2;
        w4[zrow * 65 + kf4] = Wt4[(size_t)(g * kU + u0 + uq) * 64 + kf4];
    }

    const int w = tid >> 5, lane = tid & 31;
    const int row = lane >> 2, q = lane & 3;
    const int uu = w * 2 + (q >> 1);
    const int gp = q & 1;
    const int u = u0 + uu;
    const int g0 = 2 * gp, g1 = 2 * gp + 1;

    const ulonglong2* hrow = (const ulonglong2*)(h4 + row * 65);
    const ulonglong2* wA = (const ulonglong2*)(w4 + (g0 + 4 * uu) * 65);
    const ulonglong2* wB = (const ulonglong2*)(w4 + (g1 + 4 * uu) * 65);
    const float* zbase = Zx + (size_t)(r0 + row) * kG + u;
    float* hdst = H + (size_t)(r0 + row) * kU + u;

    float creg = 0.f;
    for (int t = 0; t < kT; t++) {
        // prefetch this step's Zx values (independent of barrier)
        const float* z = zbase + (size_t)t * kB * kG;
        float z0r = __ldg(z + g0 * kU);
        float z1r = __ldg(z + g1 * kU);

        if (t > 0) {
            __syncthreads();   // all epilogue stores of step t-1 done
            if (tid == 0) {
                asm volatile("red.release.gpu.global.add.u32 [%0], %1;"
                             :: "l"(&g_bar[rg]), "r"(1u) : "memory");
                unsigned goal = (unsigned)(sync_base + t) * 16u;
                unsigned v;
                do {
                    asm volatile("ld.acquire.gpu.u32 %0, [%1];" : "=r"(v) : "l"(&g_bar[rg]));
                } while (v < goal);
            }
            __syncthreads();
        }
        // load h_t rows r0..r0+7 into smem
        const float4* hg = (const float4*)(H + (size_t)t * kB * kU + (size_t)r0 * kU);
#pragma unroll
        for (int p = 0; p < 2; p++) {
            int e = p * 256 + tid;
            int hr = e >> 6, kf4 = e & 63;
            h4[hr * 65 + kf4] = hg[hr * 64 + kf4];
        }
        __syncthreads();

        unsigned long long a0 = 0ull, a1 = 0ull;
#pragma unroll 8
        for (int k = 0; k < 64; k++) {
            ulonglong2 hv = hrow[k];
            ulonglong2 va = wA[k];
            ulonglong2 vb = wB[k];
            FMA2(a0, hv.x, va.x);
            FMA2(a1, hv.x, vb.x);
            FMA2(a0, hv.y, va.y);
            FMA2(a1, hv.y, vb.y);
        }
        float lo, hi;
        asm("mov.b64 {%0,%1}, %2;" : "=f"(lo), "=f"(hi) : "l"(a0));
        float za = z0r + lo + hi;
        asm("mov.b64 {%0,%1}, %2;" : "=f"(lo), "=f"(hi) : "l"(a1));
        float zb = z1r + lo + hi;

        float send = 0.f, ff = 0.f, oo = 0.f;
        if (gp == 0) {
            send = sigmoidf_(za) * tanhf(zb);      // sigmoid(i)*tanh(j)
        } else {
            ff = sigmoidf_(za + 1.f);              // FORGET_BIAS = 1
            oo = sigmoidf_(zb);
        }
        float ig = __shfl_xor_sync(0xffffffffu, send, 1);
        if (gp == 1) {
            creg = creg * ff + ig;
            hdst[(size_t)(t + 1) * kB * kU] = tanhf(creg) * oo;
        }
    }
}

// ---------------- fused logits GEMM (tf32 mma) + sum(exp) + target ---------
__global__ __launch_bounds__(512) void k_logits_tf32(
    const int* __restrict__ targets, const float* __restrict__ SW,
    const float* __restrict__ sb) {
    extern __shared__ float sm[];
    float* As = sm;                   // 2 buffers of 256x36
    float* Bs = sm + 2 * 256 * 36;    // 2 buffers of 32x136
    const float* __restrict__ A = g_H1 + kB * kU;
    const int tid = threadIdx.x;
    const int lane = tid & 31;
    const int w = tid >> 5;
    const int warpM = w & 7;
    const int warpN = w >> 3;
    const int m0 = blockIdx.y * 256;
    const int n0 = blockIdx.x * 128;
    const int r = lane >> 2, cq = lane & 3;

    float acc[2][8][4];
#pragma unroll
    for (int i = 0; i < 2; i++)
#pragma unroll
        for (int j = 0; j < 8; j++)
#pragma unroll
            for (int k = 0; k < 4; k++) acc[i][j][k] = 0.f;

    float4 ra[4], rb[2];
    auto loadG = [&](int kc) {
#pragma unroll
        for (int p = 0; p < 4; p++) {
            int e = p * 512 + tid;
            ra[p] = *(const float4*)&A[(size_t)(m0 + (e >> 3)) * kU + kc * 32 + (e & 7) * 4];
        }
#pragma unroll
        for (int p = 0; p < 2; p++) {
            int e = p * 512 + tid;
            rb[p] = *(const float4*)&SW[(size_t)(kc * 32 + (e >> 5)) * kV + n0 + (e & 31) * 4];
        }
    };
    auto storeS = [&](int buf) {
        float* Ab = As + buf * 256 * 36;
        float* Bb = Bs + buf * 32 * 136;
#pragma unroll
        for (int p = 0; p < 4; p++) {
            int e = p * 512 + tid;
            *(float4*)&Ab[(e >> 3) * 36 + (e & 7) * 4] = ra[p];
        }
#pragma unroll
        for (int p = 0; p < 2; p++) {
            int e = p * 512 + tid;
            *(float4*)&Bb[(e >> 5) * 136 + (e & 31) * 4] = rb[p];
        }
    };

    loadG(0);
    storeS(0);
    __syncthreads();

    for (int kc = 0; kc < 8; kc++) {
        int buf = kc & 1;
        if (kc < 7) loadG(kc + 1);
        const float* Ab = As + buf * 256 * 36;
        const float* Bb = Bs + buf * 32 * 136;
#pragma unroll
        for (int kk = 0; kk < 4; kk++) {
            uint32_t af[2][4];
#pragma unroll
            for (int mi = 0; mi < 2; mi++) {
                const float* ap = &Ab[(warpM * 32 + mi * 16 + r) * 36 + kk * 8 + cq];
                af[mi][0] = f2tf32(ap[0]);
                af[mi][1] = f2tf32(ap[8 * 36]);
                af[mi][2] = f2tf32(ap[4]);
                af[mi][3] = f2tf32(ap[8 * 36 + 4]);
            }
#pragma unroll
            for (int ni = 0; ni < 8; ni++) {
                const float* bp = &Bb[(kk * 8 + cq) * 136 + warpN * 64 + ni * 8 + r];
                uint32_t b0 = f2tf32(bp[0]);
                uint32_t b1 = f2tf32(bp[4 * 136]);
#pragma unroll
                for (int mi = 0; mi < 2; mi++) {
                    asm volatile(
                        "mma.sync.aligned.m16n8k8.row.col.f32.tf32.tf32.f32 "
                        "{%0,%1,%2,%3}, {%4,%5,%6,%7}, {%8,%9}, {%0,%1,%2,%3};\n"
                        : "+f"(acc[mi][ni][0]), "+f"(acc[mi][ni][1]),
                          "+f"(acc[mi][ni][2]), "+f"(acc[mi][ni][3])
                        : "r"(af[mi][0]), "r"(af[mi][1]), "r"(af[mi][2]), "r"(af[mi][3]),
                          "r"(b0), "r"(b1));
                }
            }
        }
        if (kc < 7) { storeS(buf ^ 1); __syncthreads(); }
    }

    // epilogue: bias, target grab, sum(exp) per row over this warp's 64 cols
#pragma unroll
    for (int mi = 0; mi < 2; mi++) {
#pragma unroll
        for (int hh = 0; hh < 2; hh++) {
            int gm = m0 + warpM * 32 + mi * 16 + r + 8 * hh;
            int tt = gm >> 6, bb = gm & 63;
            int tg = targets[bb * kT + tt];
            float s = 0.f;
#pragma unroll
            for (int ni = 0; ni < 8; ni++) {
                int col = n0 + warpN * 64 + ni * 8 + cq * 2;
                float l0 = acc[mi][ni][hh * 2 + 0] + sb[col];
                float l1 = acc[mi][ni][hh * 2 + 1] + sb[col + 1];
                if (col == tg) g_TL[gm] = l0;
                if (col + 1 == tg) g_TL[gm] = l1;
                s += __expf(l0) + __expf(l1);
            }
            s += __shfl_xor_sync(0xffffffffu, s, 1);
            s += __shfl_xor_sync(0xffffffffu, s, 2);
            if (cq == 0) atomicAdd(&g_S[gm], s);
        }
    }
}

// ---------------- final: cost = mean(log(S) - target_logit) ----------------
__global__ void k_final(float* __restrict__ out) {
    __shared__ float red[256];
    int tid = threadIdx.x;
    float acc = 0.f;
    for (int rr = tid; rr < kM; rr += 256) acc += logf(g_S[rr]) - g_TL[rr];
    red[tid] = acc;
    __syncthreads();
    for (int s = 128; s > 0; s >>= 1) {
        if (tid < s) red[tid] += red[tid + s];
        __syncthreads();
    }
    if (tid == 0) out[0] = red[0] / (float)kM;
}

// ---------------- launch ----------------------------------------------------
extern "C" void kernel_launch(void* const* d_in, const int* in_sizes, int n_in,
                              void* d_out, int out_size) {
    const int*   input_data = (const int*)d_in[0];
    const int*   targets    = (const int*)d_in[1];
    const float* emb        = (const float*)d_in[2];
    const float* W0         = (const float*)d_in[3];
    const float* b0         = (const float*)d_in[4];
    const float* W1         = (const float*)d_in[5];
    const float* b1         = (const float*)d_in[6];
    const float* sw         = (const float*)d_in[7];
    const float* sb         = (const float*)d_in[8];
    float* out = (float*)d_out;

    const int lstm_smem   = (64 * 65 + 8 * 65) * 16;              // 74880 B
    const int gemm_smem   = (2 * 256 * 36 + 2 * 32 * 136) * 4;    // 108544 B
    cudaFuncSetAttribute(k_lstm_layer, cudaFuncAttributeMaxDynamicSharedMemorySize, lstm_smem);
    cudaFuncSetAttribute(k_gemm_zx_tf32, cudaFuncAttributeMaxDynamicSharedMemorySize, gemm_smem);
    cudaFuncSetAttribute(k_logits_tf32, cudaFuncAttributeMaxDynamicSharedMemorySize, gemm_smem);

    // launch order puts k_lstm_layer(layer 0) at index 3 — ncu's capture slot
    k_init<<<64, 256>>>();                                              // 0
    k_transpose<<<dim3(32, 8), dim3(32, 8)>>>(W0, 0);                   // 1
    k_gemm_zx_tf32<<<dim3(8, 32), 512, gemm_smem>>>(0, input_data, emb, W0, b0);  // 2
    k_lstm_layer<<<128, 256, lstm_smem>>>(0, 0);                        // 3
    k_transpose<<<dim3(32, 8), dim3(32, 8)>>>(W1, 1);                   // 4
    k_gemm_zx_tf32<<<dim3(8, 32), 512, gemm_smem>>>(1, input_data, emb, W1, b1);  // 5
    k_lstm_layer<<<128, 256, lstm_smem>>>(1, kT - 1);                   // 6
    k_logits_tf32<<<dim3(125, 32), 512, gemm_smem>>>(targets, sw, sb);  // 7
    k_final<<<1, 256>>>(out);                                           // 8
}

// round 5
// speedup vs baseline: 2.3193x; 1.0033x over previous
#include <cuda_runtime.h>
#include <math.h>
#include <stdint.h>

#define kB 64
#define kT 128
#define kU 256
#define kV 16000
#define kG 1024   /* 4*U */
#define kM 8192   /* B*T */

// ---------------- scratch (device globals; no allocation allowed) ----------
__device__ __align__(16) float g_Z0x[kT * kB * kG];
__device__ __align__(16) float g_Z1x[kT * kB * kG];
__device__ __align__(16) float g_H0[(kT + 1) * kB * kU];
__device__ __align__(16) float g_H1[(kT + 1) * kB * kU];
__device__ __align__(16) float g_Wt0[kG * kU];
__device__ __align__(16) float g_Wt1[kG * kU];
__device__ float g_S[kM];
__device__ float g_TL[kM];
__device__ unsigned g_bar[8];

__device__ __forceinline__ float sigmoidf_(float x) { return 1.f / (1.f + __expf(-x)); }

__device__ __forceinline__ uint32_t f2tf32(float x) {
    uint32_t u; asm("cvt.rna.tf32.f32 %0, %1;" : "=r"(u) : "f"(x)); return u;
}

#define FMA2(acc, a, b) \
    asm("fma.rn.f32x2 %0, %1, %2, %0;" : "+l"(acc) : "l"(a), "l"(b))

// ---------------- init: zero states + sums + barriers -----------------------
__global__ void k_init() {
    int i = blockIdx.x * 256 + threadIdx.x;
    if (i < kB * kU) { g_H0[i] = 0.f; g_H1[i] = 0.f; }
    if (i < kM) g_S[i] = 0.f;
    if (i < 8) g_bar[i] = 0u;
}

// ---------------- transpose h-part of W: Wt[col][k] = W[U+k][col] ----------
__global__ void k_transpose(const float* __restrict__ W, int layer) {
    __shared__ float tile[32][33];
    float* Wt = layer ? g_Wt1 : g_Wt0;
    int col0 = blockIdx.x * 32, k0 = blockIdx.y * 32;
#pragma unroll
    for (int i = threadIdx.y; i < 32; i += 8)
        tile[i][threadIdx.x] = W[(kU + k0 + i) * kG + col0 + threadIdx.x];
    __syncthreads();
#pragma unroll
    for (int i = threadIdx.y; i < 32; i += 8)
        Wt[(long)(col0 + i) * kU + k0 + threadIdx.x] = tile[threadIdx.x][i];
}

// ---------------- Zx GEMM (tf32 mma, staged cvt): Z = A @ W_x + bias -------
__global__ __launch_bounds__(512) void k_gemm_zx_tf32(
    int layer, const int* __restrict__ input_data, const float* __restrict__ emb,
    const float* __restrict__ W, const float* __restrict__ bias) {
    extern __shared__ uint32_t sm[];
    uint32_t* As = sm;                   // 2 buffers of 256x36 (tf32 bits)
    uint32_t* Bs = sm + 2 * 256 * 36;    // 2 buffers of 32x136
    __shared__ const float* rowp[256];
    float* Z = layer ? g_Z1x : g_Z0x;
    const int tid = threadIdx.x;
    const int lane = tid & 31;
    const int w = tid >> 5;
    const int warpM = w & 7;
    const int warpN = w >> 3;
    const int m0 = blockIdx.y * 256;
    const int n0 = blockIdx.x * 128;
    const int r = lane >> 2, cq = lane & 3;

    if (tid < 256) {
        int m = m0 + tid;
        if (layer == 0) {
            int t = m >> 6, b = m & 63;
            rowp[tid] = emb + (size_t)input_data[b * kT + t] * kU;
        } else {
            rowp[tid] = g_H0 + kB * kU + (size_t)m * kU;
        }
    }
    __syncthreads();

    float acc[2][8][4];
#pragma unroll
    for (int i = 0; i < 2; i++)
#pragma unroll
        for (int j = 0; j < 8; j++)
#pragma unroll
            for (int k = 0; k < 4; k++) acc[i][j][k] = 0.f;

    float4 ra[4], rb[2];
    auto loadG = [&](int kc) {
#pragma unroll
        for (int p = 0; p < 4; p++) {
            int e = p * 512 + tid;
            ra[p] = *(const float4*)&rowp[e >> 3][kc * 32 + (e & 7) * 4];
        }
#pragma unroll
        for (int p = 0; p < 2; p++) {
            int e = p * 512 + tid;
            rb[p] = *(const float4*)&W[(size_t)(kc * 32 + (e >> 5)) * kG + n0 + (e & 31) * 4];
        }
    };
    auto storeS = [&](int buf) {
        uint32_t* Ab = As + buf * 256 * 36;
        uint32_t* Bb = Bs + buf * 32 * 136;
#pragma unroll
        for (int p = 0; p < 4; p++) {
            int e = p * 512 + tid;
            uint4 v = make_uint4(f2tf32(ra[p].x), f2tf32(ra[p].y), f2tf32(ra[p].z), f2tf32(ra[p].w));
            *(uint4*)&Ab[(e >> 3) * 36 + (e & 7) * 4] = v;
        }
#pragma unroll
        for (int p = 0; p < 2; p++) {
            int e = p * 512 + tid;
            uint4 v = make_uint4(f2tf32(rb[p].x), f2tf32(rb[p].y), f2tf32(rb[p].z), f2tf32(rb[p].w));
            *(uint4*)&Bb[(e >> 5) * 136 + (e & 31) * 4] = v;
        }
    };

    loadG(0);
    storeS(0);
    __syncthreads();

    for (int kc = 0; kc < 8; kc++) {
        int buf = kc & 1;
        if (kc < 7) loadG(kc + 1);
        const uint32_t* Ab = As + buf * 256 * 36;
        const uint32_t* Bb = Bs + buf * 32 * 136;
#pragma unroll
        for (int kk = 0; kk < 4; kk++) {
            uint32_t af[2][4];
#pragma unroll
            for (int mi = 0; mi < 2; mi++) {
                const uint32_t* ap = &Ab[(warpM * 32 + mi * 16 + r) * 36 + kk * 8 + cq];
                af[mi][0] = ap[0];
                af[mi][1] = ap[8 * 36];
                af[mi][2] = ap[4];
                af[mi][3] = ap[8 * 36 + 4];
            }
#pragma unroll
            for (int ni = 0; ni < 8; ni++) {
                const uint32_t* bp = &Bb[(kk * 8 + cq) * 136 + warpN * 64 + ni * 8 + r];
                uint32_t b0 = bp[0];
                uint32_t b1 = bp[4 * 136];
#pragma unroll
                for (int mi = 0; mi < 2; mi++) {
                    asm volatile(
                        "mma.sync.aligned.m16n8k8.row.col.f32.tf32.tf32.f32 "
                        "{%0,%1,%2,%3}, {%4,%5,%6,%7}, {%8,%9}, {%0,%1,%2,%3};\n"
                        : "+f"(acc[mi][ni][0]), "+f"(acc[mi][ni][1]),
                          "+f"(acc[mi][ni][2]), "+f"(acc[mi][ni][3])
                        : "r"(af[mi][0]), "r"(af[mi][1]), "r"(af[mi][2]), "r"(af[mi][3]),
                          "r"(b0), "r"(b1));
                }
            }
        }
        if (kc < 7) { storeS(buf ^ 1); __syncthreads(); }
    }

    // epilogue: + bias, store Z
#pragma unroll
    for (int ni = 0; ni < 8; ni++) {
        int col = n0 + warpN * 64 + ni * 8 + cq * 2;
        float2 bb = *(const float2*)&bias[col];
#pragma unroll
        for (int mi = 0; mi < 2; mi++) {
            int gm = m0 + warpM * 32 + mi * 16 + r;
            *(float2*)&Z[(size_t)gm * kG + col] =
                make_float2(acc[mi][ni][0] + bb.x, acc[mi][ni][1] + bb.y);
            *(float2*)&Z[(size_t)(gm + 8) * kG + col] =
                make_float2(acc[mi][ni][2] + bb.x, acc[mi][ni][3] + bb.y);
        }
    }
}

// ---------------- persistent LSTM layer -------------------------------------
// 128 blocks = 8 row-groups x 16 u-blocks, 512 threads (16 warps).
// Warp = one u-column; lane = (row 0..7, gate-pair gp, K-half kh).
// Each thread: 2 half-K dot products; combine via shuffles (kh, then gp).
__global__ __launch_bounds__(512) void k_lstm_layer(int layer, int sync_base) {
    extern __shared__ char smraw[];
    float4* w4 = (float4*)smraw;           // 64 x 65
    float4* h4 = w4 + 64 * 65;             // 8 x 65

    const int tid = threadIdx.x;
    const int bx = blockIdx.x;
    const int rg = bx >> 4, ub = bx & 15;
    const int r0 = rg * 8, u0 = ub * 16;
    const float* Zx = layer ? g_Z1x : g_Z0x;
    const float* Wt = layer ? g_Wt1 : g_Wt0;
    float* H = layer ? g_H1 : g_H0;
    const float4* Wt4 = (const float4*)Wt;

    // load 64 weight rows once; storage idx = g + 4*uq
#pragma unroll
    for (int p = 0; p < 8; p++) {
        int e = p * 512 + tid;
        int zrow = e >> 6, kf4 = e & 63;
        int g = zrow & 3, uq = zrow >> 2;
        w4[zrow * 65 + kf4] = Wt4[(size_t)(g * kU + u0 + uq) * 64 + kf4];
    }

    const int w = tid >> 5, lane = tid & 31;
    const int row = lane >> 2;
    const int gp = (lane >> 1) & 1;
    const int kh = lane & 1;
    const int uu = w;
    const int u = u0 + uu;
    const int g0 = 2 * gp, g1 = 2 * gp + 1;

    const ulonglong2* hrow = (const ulonglong2*)(h4 + row * 65 + kh * 32);
    const ulonglong2* wA = (const ulonglong2*)(w4 + (g0 + 4 * uu) * 65 + kh * 32);
    const ulonglong2* wB = (const ulonglong2*)(w4 + (g1 + 4 * uu) * 65 + kh * 32);
    const float* zbase = Zx + (size_t)(r0 + row) * kG + u;
    float* hdst = H + (size_t)(r0 + row) * kU + u;

    float creg = 0.f;
    for (int t = 0; t < kT; t++) {
        // prefetch this step's Zx values (independent of barrier)
        const float* z = zbase + (size_t)t * kB * kG;
        float z0r = __ldg(z + g0 * kU);
        float z1r = __ldg(z + g1 * kU);

        if (t > 0) {
            __syncthreads();   // all h stores of step t-1 done
            if (tid == 0) {
                asm volatile("red.release.gpu.global.add.u32 [%0], %1;"
                             :: "l"(&g_bar[rg]), "r"(1u) : "memory");
                unsigned goal = (unsigned)(sync_base + t) * 16u;
                unsigned v;
                do {
                    asm volatile("ld.acquire.gpu.u32 %0, [%1];" : "=r"(v) : "l"(&g_bar[rg]));
                } while (v < goal);
            }
            __syncthreads();
        }
        // load h_t rows r0..r0+7 into smem (512 float4, one per thread)
        {
            const float4* hg = (const float4*)(H + (size_t)t * kB * kU + (size_t)r0 * kU);
            int hr = tid >> 6, kf4 = tid & 63;
            h4[hr * 65 + kf4] = hg[hr * 64 + kf4];
        }
        __syncthreads();

        unsigned long long a0 = 0ull, a1 = 0ull;
#pragma unroll
        for (int k = 0; k < 16; k++) {
            ulonglong2 hv = hrow[k];
            ulonglong2 va = wA[k];
            ulonglong2 vb = wB[k];
            FMA2(a0, hv.x, va.x);
            FMA2(a1, hv.x, vb.x);
            FMA2(a0, hv.y, va.y);
            FMA2(a1, hv.y, vb.y);
        }
        float lo, hi;
        asm("mov.b64 {%0,%1}, %2;" : "=f"(lo), "=f"(hi) : "l"(a0));
        float s0 = lo + hi;
        asm("mov.b64 {%0,%1}, %2;" : "=f"(lo), "=f"(hi) : "l"(a1));
        float s1 = lo + hi;
        // combine K halves (lanes kh=0/1)
        s0 += __shfl_xor_sync(0xffffffffu, s0, 1);
        s1 += __shfl_xor_sync(0xffffffffu, s1, 1);

        float za = z0r + s0;
        float zb = z1r + s1;

        float send = 0.f, ff = 0.f, oo = 0.f;
        if (gp == 0) {
            send = sigmoidf_(za) * tanhf(zb);      // sigmoid(i)*tanh(j)
        } else {
            ff = sigmoidf_(za + 1.f);              // FORGET_BIAS = 1
            oo = sigmoidf_(zb);
        }
        float ig = __shfl_xor_sync(0xffffffffu, send, 2);
        if (gp == 1) {
            creg = creg * ff + ig;                 // both kh lanes track same c
            if (kh == 0)
                hdst[(size_t)(t + 1) * kB * kU] = tanhf(creg) * oo;
        }
    }
}

// ---------------- fused logits GEMM (tf32 mma, staged cvt) -----------------
__global__ __launch_bounds__(512) void k_logits_tf32(
    const int* __restrict__ targets, const float* __restrict__ SW,
    const float* __restrict__ sb) {
    extern __shared__ uint32_t sm[];
    uint32_t* As = sm;                   // 2 buffers of 256x36
    uint32_t* Bs = sm + 2 * 256 * 36;    // 2 buffers of 32x136
    const float* __restrict__ A = g_H1 + kB * kU;
    const int tid = threadIdx.x;
    const int lane = tid & 31;
    const int w = tid >> 5;
    const int warpM = w & 7;
    const int warpN = w >> 3;
    const int m0 = blockIdx.y * 256;
    const int n0 = blockIdx.x * 128;
    const int r = lane >> 2, cq = lane & 3;

    float acc[2][8][4];
#pragma unroll
    for (int i = 0; i < 2; i++)
#pragma unroll
        for (int j = 0; j < 8; j++)
#pragma unroll
            for (int k = 0; k < 4; k++) acc[i][j][k] = 0.f;

    float4 ra[4], rb[2];
    auto loadG = [&](int kc) {
#pragma unroll
        for (int p = 0; p < 4; p++) {
            int e = p * 512 + tid;
            ra[p] = *(const float4*)&A[(size_t)(m0 + (e >> 3)) * kU + kc * 32 + (e & 7) * 4];
        }
#pragma unroll
        for (int p = 0; p < 2; p++) {
            int e = p * 512 + tid;
            rb[p] = *(const float4*)&SW[(size_t)(kc * 32 + (e >> 5)) * kV + n0 + (e & 31) * 4];
        }
    };
    auto storeS = [&](int buf) {
        uint32_t* Ab = As + buf * 256 * 36;
        uint32_t* Bb = Bs + buf * 32 * 136;
#pragma unroll
        for (int p = 0; p < 4; p++) {
            int e = p * 512 + tid;
            uint4 v = make_uint4(f2tf32(ra[p].x), f2tf32(ra[p].y), f2tf32(ra[p].z), f2tf32(ra[p].w));
            *(uint4*)&Ab[(e >> 3) * 36 + (e & 7) * 4] = v;
        }
#pragma unroll
        for (int p = 0; p < 2; p++) {
            int e = p * 512 + tid;
            uint4 v = make_uint4(f2tf32(rb[p].x), f2tf32(rb[p].y), f2tf32(rb[p].z), f2tf32(rb[p].w));
            *(uint4*)&Bb[(e >> 5) * 136 + (e & 31) * 4] = v;
        }
    };

    loadG(0);
    storeS(0);
    __syncthreads();

    for (int kc = 0; kc < 8; kc++) {
        int buf = kc & 1;
        if (kc < 7) loadG(kc + 1);
        const uint32_t* Ab = As + buf * 256 * 36;
        const uint32_t* Bb = Bs + buf * 32 * 136;
#pragma unroll
        for (int kk = 0; kk < 4; kk++) {
            uint32_t af[2][4];
#pragma unroll
            for (int mi = 0; mi < 2; mi++) {
                const uint32_t* ap = &Ab[(warpM * 32 + mi * 16 + r) * 36 + kk * 8 + cq];
                af[mi][0] = ap[0];
                af[mi][1] = ap[8 * 36];
                af[mi][2] = ap[4];
                af[mi][3] = ap[8 * 36 + 4];
            }
#pragma unroll
            for (int ni = 0; ni < 8; ni++) {
                const uint32_t* bp = &Bb[(kk * 8 + cq) * 136 + warpN * 64 + ni * 8 + r];
                uint32_t b0 = bp[0];
                uint32_t b1 = bp[4 * 136];
#pragma unroll
                for (int mi = 0; mi < 2; mi++) {
                    asm volatile(
                        "mma.sync.aligned.m16n8k8.row.col.f32.tf32.tf32.f32 "
                        "{%0,%1,%2,%3}, {%4,%5,%6,%7}, {%8,%9}, {%0,%1,%2,%3};\n"
                        : "+f"(acc[mi][ni][0]), "+f"(acc[mi][ni][1]),
                          "+f"(acc[mi][ni][2]), "+f"(acc[mi][ni][3])
                        : "r"(af[mi][0]), "r"(af[mi][1]), "r"(af[mi][2]), "r"(af[mi][3]),
                          "r"(b0), "r"(b1));
                }
            }
        }
        if (kc < 7) { storeS(buf ^ 1); __syncthreads(); }
    }

    // epilogue: bias, target grab, sum(exp) per row over this warp's 64 cols
#pragma unroll
    for (int mi = 0; mi < 2; mi++) {
#pragma unroll
        for (int hh = 0; hh < 2; hh++) {
            int gm = m0 + warpM * 32 + mi * 16 + r + 8 * hh;
            int tt = gm >> 6, bb = gm & 63;
            int tg = targets[bb * kT + tt];
            float s = 0.f;
#pragma unroll
            for (int ni = 0; ni < 8; ni++) {
                int col = n0 + warpN * 64 + ni * 8 + cq * 2;
                float l0 = acc[mi][ni][hh * 2 + 0] + sb[col];
                float l1 = acc[mi][ni][hh * 2 + 1] + sb[col + 1];
                if (col == tg) g_TL[gm] = l0;
                if (col + 1 == tg) g_TL[gm] = l1;
                s += __expf(l0) + __expf(l1);
            }
            s += __shfl_xor_sync(0xffffffffu, s, 1);
            s += __shfl_xor_sync(0xffffffffu, s, 2);
            if (cq == 0) atomicAdd(&g_S[gm], s);
        }
    }
}

// ---------------- final: cost = mean(log(S) - target_logit) ----------------
__global__ void k_final(float* __restrict__ out) {
    __shared__ float red[256];
    int tid = threadIdx.x;
    float acc = 0.f;
    for (int rr = tid; rr < kM; rr += 256) acc += logf(g_S[rr]) - g_TL[rr];
    red[tid] = acc;
    __syncthreads();
    for (int s = 128; s > 0; s >>= 1) {
        if (tid < s) red[tid] += red[tid + s];
        __syncthreads();
    }
    if (tid == 0) out[0] = red[0] / (float)kM;
}

// ---------------- launch ----------------------------------------------------
extern "C" void kernel_launch(void* const* d_in, const int* in_sizes, int n_in,
                              void* d_out, int out_size) {
    const int*   input_data = (const int*)d_in[0];
    const int*   targets    = (const int*)d_in[1];
    const float* emb        = (const float*)d_in[2];
    const float* W0         = (const float*)d_in[3];
    const float* b0         = (const float*)d_in[4];
    const float* W1         = (const float*)d_in[5];
    const float* b1         = (const float*)d_in[6];
    const float* sw         = (const float*)d_in[7];
    const float* sb         = (const float*)d_in[8];
    float* out = (float*)d_out;

    const int lstm_smem   = (64 * 65 + 8 * 65) * 16;              // 74880 B
    const int gemm_smem   = (2 * 256 * 36 + 2 * 32 * 136) * 4;    // 108544 B
    cudaFuncSetAttribute(k_lstm_layer, cudaFuncAttributeMaxDynamicSharedMemorySize, lstm_smem);
    cudaFuncSetAttribute(k_gemm_zx_tf32, cudaFuncAttributeMaxDynamicSharedMemorySize, gemm_smem);
    cudaFuncSetAttribute(k_logits_tf32, cudaFuncAttributeMaxDynamicSharedMemorySize, gemm_smem);

    // launch order keeps k_lstm_layer(layer 0) at index 3 — ncu's capture slot
    k_init<<<64, 256>>>();                                              // 0
    k_transpose<<<dim3(32, 8), dim3(32, 8)>>>(W0, 0);                   // 1
    k_gemm_zx_tf32<<<dim3(8, 32), 512, gemm_smem>>>(0, input_data, emb, W0, b0);  // 2
    k_lstm_layer<<<128, 512, lstm_smem>>>(0, 0);                        // 3
    k_transpose<<<dim3(32, 8), dim3(32, 8)>>>(W1, 1);                   // 4
    k_gemm_zx_tf32<<<dim3(8, 32), 512, gemm_smem>>>(1, input_data, emb, W1, b1);  // 5
    k_lstm_layer<<<128, 512, lstm_smem>>>(1, kT - 1);                   // 6
    k_logits_tf32<<<dim3(125, 32), 512, gemm_smem>>>(targets, sw, sb);  // 7
    k_final<<<1, 256>>>(out);                                           // 8
}